// round 5
// baseline (speedup 1.0000x reference)
#include <cuda_runtime.h>
#include <cstdint>

// ---------------------------------------------------------------------------
// C[4096,18432] = A[4096,7168] * W[18432,7168]^T, per-128x128 block scales.
//  Pass 1: pack kernels -> dequant + cvt.rna.tf32 + SW128 swizzle, tile-major
//          (coalesced STG.128 stores — R3 layout).
//  Pass 2: GEMM -> mma.sync.m16n8k8 tf32, cp.async 2-stage pipeline,
//          2 CTAs/SM (98KB smem each) to fill issue bubbles.
// ---------------------------------------------------------------------------

#define MDIM 4096
#define NDIM 18432
#define KDIM 7168
#define BM 128
#define BN 256
#define BK 32
#define KCHUNKS (KDIM / BK)          // 224
#define MTILES (MDIM / BM)           // 32
#define NTILES (NDIM / BN)           // 72
#define STAGES 2

#define A_TILE_BYTES (BM * 128)      // 16384 (128 rows x 32 tf32, SW128)
#define W_TILE_BYTES (BN * 128)      // 32768 (256 rows x 32 tf32, SW128)
#define STAGE_BYTES  (A_TILE_BYTES + W_TILE_BYTES)     // 49152
#define SMEM_TOTAL   (STAGES * STAGE_BYTES)            // 98304 -> 2 CTAs/SM

__device__ __align__(1024) unsigned char g_ap[(size_t)MDIM * KDIM * 4];
__device__ __align__(1024) unsigned char g_wp[(size_t)NDIM * KDIM * 4];

// ---------------------------------------------------------------------------
__device__ __forceinline__ uint32_t smem_u32(const void* p) {
    uint32_t a;
    asm("{ .reg .u64 t; cvta.to.shared.u64 t, %1; cvt.u32.u64 %0, t; }" : "=r"(a) : "l"(p));
    return a;
}
__device__ __forceinline__ float rna_tf32(float x) {
    uint32_t u;
    asm("cvt.rna.tf32.f32 %0, %1;" : "=r"(u) : "f"(x));
    return __uint_as_float(u);
}
__device__ __forceinline__ uint32_t lds32(uint32_t a) {
    uint32_t v;
    asm volatile("ld.shared.b32 %0, [%1];" : "=r"(v) : "r"(a));
    return v;
}
__device__ __forceinline__ void cp16(uint32_t dst, const void* src) {
    asm volatile("cp.async.cg.shared.global [%0], [%1], 16;"
                 :: "r"(dst), "l"(__cvta_generic_to_global(src)) : "memory");
}
__device__ __forceinline__ void mma_tf32(float* d, const uint32_t* a, const uint32_t* b) {
    asm volatile(
        "mma.sync.aligned.m16n8k8.row.col.f32.tf32.tf32.f32 "
        "{%0,%1,%2,%3}, {%4,%5,%6,%7}, {%8,%9}, {%0,%1,%2,%3};"
        : "+f"(d[0]), "+f"(d[1]), "+f"(d[2]), "+f"(d[3])
        : "r"(a[0]), "r"(a[1]), "r"(a[2]), "r"(a[3]), "r"(b[0]), "r"(b[1]));
}

// ---------------------------------------------------------------------------
// Pack kernels (R3 layout): tile = rows x 32 tf32, 128B/row, SW128 swizzle:
// byte = row*128 + k*4, sw = byte ^ ((byte>>3)&0x70). Coalesced STG.128.
// ---------------------------------------------------------------------------
__global__ __launch_bounds__(256) void pack_a_kernel(const float* __restrict__ x) {
    size_t i = (size_t)blockIdx.x * 256 + threadIdx.x;
    if (i >= (size_t)MDIM * KDIM / 4) return;
    size_t f = i * 4;
    int m = (int)(f / KDIM);
    int k = (int)(f % KDIM);
    float4 v = *(const float4*)(x + f);
    uint32_t off = ((uint32_t)(m & 127) << 7) + ((uint32_t)(k & 31) << 2);
    uint32_t sw = off ^ ((off >> 3) & 0x70);
    unsigned char* dst = g_ap + ((size_t)(m >> 7) * KCHUNKS + (k >> 5)) * A_TILE_BYTES + sw;
    *(float4*)dst = make_float4(rna_tf32(v.x), rna_tf32(v.y), rna_tf32(v.z), rna_tf32(v.w));
}

__global__ __launch_bounds__(256) void pack_w_kernel(const float* __restrict__ w,
                                                     const float* __restrict__ scale) {
    size_t i = (size_t)blockIdx.x * 256 + threadIdx.x;
    if (i >= (size_t)NDIM * KDIM / 4) return;
    size_t f = i * 4;
    int n = (int)(f / KDIM);
    int k = (int)(f % KDIM);
    float4 v = *(const float4*)(w + f);
    float s = scale[(size_t)(n >> 7) * (KDIM / 128) + (k >> 7)];
    uint32_t off = ((uint32_t)(n & 255) << 7) + ((uint32_t)(k & 31) << 2);
    uint32_t sw = off ^ ((off >> 3) & 0x70);
    unsigned char* dst = g_wp + ((size_t)(n >> 8) * KCHUNKS + (k >> 5)) * W_TILE_BYTES + sw;
    *(float4*)dst = make_float4(rna_tf32(v.x * s), rna_tf32(v.y * s),
                                rna_tf32(v.z * s), rna_tf32(v.w * s));
}

// ---------------------------------------------------------------------------
// GEMM: 8 warps (2m x 4n), warp tile 64x64, mma m16n8k8 tf32, 2 CTAs/SM.
// ---------------------------------------------------------------------------
__global__ __launch_bounds__(256, 2) void gemm_tf32_kernel(float* __restrict__ C) {
    extern __shared__ __align__(1024) unsigned char smem[];
    const uint32_t sb = smem_u32(smem);
    const int tid = threadIdx.x;
    const int wid = tid >> 5;
    const int lane = tid & 31;

    // Grid swizzle: 8-wide n groups for L2 reuse.
    const int GN = 8;
    int bid = blockIdx.x;
    int grp = bid / (MTILES * GN);
    int rem = bid % (MTILES * GN);
    int bm = rem / GN;
    int bn = grp * GN + rem % GN;

    const unsigned char* aP = g_ap + (size_t)bm * KCHUNKS * A_TILE_BYTES;
    const unsigned char* wP = g_wp + (size_t)bn * KCHUNKS * W_TILE_BYTES;

    const int tr = lane >> 2;            // 0..7
    const int tc = lane & 3;             // 0..3
    const int wm = wid & 1;
    const int wn = wid >> 1;
    const int m_base = wm * 64;
    const int n_base = wn * 64;

    // Relative smem byte addresses (SW128 swizzle: group XOR reduces to ^tr).
    uint32_t baseA0[4], baseA1[4], baseB[8];
#pragma unroll
    for (int mi = 0; mi < 4; mi++) {
        baseA0[mi] = (uint32_t)(m_base + mi * 16 + tr) * 128 + tc * 4;
        baseA1[mi] = baseA0[mi] + 8 * 128;
    }
#pragma unroll
    for (int ni = 0; ni < 8; ni++)
        baseB[ni] = (uint32_t)A_TILE_BYTES + (uint32_t)(n_base + ni * 8 + tr) * 128 + tc * 4;

    float acc[4][8][4];
#pragma unroll
    for (int mi = 0; mi < 4; mi++)
#pragma unroll
        for (int ni = 0; ni < 8; ni++)
#pragma unroll
            for (int q = 0; q < 4; q++) acc[mi][ni][q] = 0.f;

    auto issue = [&](int c) {
        if (c < KCHUNKS) {
            const unsigned char* srcA = aP + (size_t)c * A_TILE_BYTES;
            const unsigned char* srcW = wP + (size_t)c * W_TILE_BYTES;
            uint32_t dst = sb + (uint32_t)(c & (STAGES - 1)) * STAGE_BYTES;
#pragma unroll
            for (int i = 0; i < 4; i++) {
                int idx = tid + i * 256;
                cp16(dst + idx * 16, srcA + idx * 16);
            }
#pragma unroll
            for (int i = 0; i < 8; i++) {
                int idx = tid + i * 256;
                cp16(dst + A_TILE_BYTES + idx * 16, srcW + idx * 16);
            }
        }
        asm volatile("cp.async.commit_group;" ::: "memory");
    };

    // Prologue: fill both stages.
    issue(0);
    issue(1);

#pragma unroll 1
    for (int c = 0; c < KCHUNKS; c++) {
        asm volatile("cp.async.wait_group 1;" ::: "memory");
        __syncthreads();

        const uint32_t st = sb + (uint32_t)(c & (STAGES - 1)) * STAGE_BYTES;
#pragma unroll
        for (int ks = 0; ks < 4; ks++) {
            const uint32_t offe = (uint32_t)((2 * ks) ^ tr) << 4;
            const uint32_t offo = offe ^ 16;
            uint32_t a[4][4];
#pragma unroll
            for (int mi = 0; mi < 4; mi++) {
                a[mi][0] = lds32(st + baseA0[mi] + offe);
                a[mi][1] = lds32(st + baseA1[mi] + offe);
                a[mi][2] = lds32(st + baseA0[mi] + offo);
                a[mi][3] = lds32(st + baseA1[mi] + offo);
            }
            uint32_t b[8][2];
#pragma unroll
            for (int ni = 0; ni < 8; ni++) {
                b[ni][0] = lds32(st + baseB[ni] + offe);
                b[ni][1] = lds32(st + baseB[ni] + offo);
            }
#pragma unroll
            for (int mi = 0; mi < 4; mi++)
#pragma unroll
                for (int ni = 0; ni < 8; ni++)
                    mma_tf32(acc[mi][ni], a[mi], b[ni]);
        }
        __syncthreads();          // required: issue(c+2) overwrites stage c&1
        issue(c + 2);
    }

    // Epilogue.
#pragma unroll
    for (int mi = 0; mi < 4; mi++) {
        size_t r0 = (size_t)bm * BM + m_base + mi * 16 + tr;
        float* p0 = C + r0 * NDIM + (size_t)bn * BN + n_base + 2 * tc;
        float* p1 = p0 + (size_t)8 * NDIM;
#pragma unroll
        for (int ni = 0; ni < 8; ni++) {
            *(float2*)(p0 + ni * 8) = make_float2(acc[mi][ni][0], acc[mi][ni][1]);
            *(float2*)(p1 + ni * 8) = make_float2(acc[mi][ni][2], acc[mi][ni][3]);
        }
    }
}

// ---------------------------------------------------------------------------
extern "C" void kernel_launch(void* const* d_in, const int* in_sizes, int n_in,
                              void* d_out, int out_size) {
    const float* x      = (const float*)d_in[0];
    const float* weight = (const float*)d_in[1];
    const float* scale  = (const float*)d_in[2];
    float* out          = (float*)d_out;

    cudaFuncSetAttribute(gemm_tf32_kernel,
                         cudaFuncAttributeMaxDynamicSharedMemorySize, SMEM_TOTAL);

    size_t a4 = (size_t)MDIM * KDIM / 4;
    size_t w4 = (size_t)NDIM * KDIM / 4;
    pack_a_kernel<<<(unsigned)((a4 + 255) / 256), 256>>>(x);
    pack_w_kernel<<<(unsigned)((w4 + 255) / 256), 256>>>(weight, scale);
    gemm_tf32_kernel<<<MTILES * NTILES, 256, SMEM_TOTAL>>>(out);
}

// round 6
// speedup vs baseline: 3.2582x; 3.2582x over previous
#include <cuda_runtime.h>
#include <cstdint>

// ---------------------------------------------------------------------------
// C[4096,18432] = A[4096,7168] * W[18432,7168]^T, per-128x128 block scales.
//  Pass 1: pack kernels -> dequant + cvt.rna.tf32 + SW128 swizzle, tile-major.
//  Pass 2: GEMM -> mma.sync.m16n8k8 tf32, 4-stage pipeline fed by
//          cp.async.bulk (2 instrs/chunk from thread 0) + mbarrier parity.
// ---------------------------------------------------------------------------

#define MDIM 4096
#define NDIM 18432
#define KDIM 7168
#define BM 128
#define BN 256
#define BK 32
#define KCHUNKS (KDIM / BK)          // 224
#define MTILES (MDIM / BM)           // 32
#define NTILES (NDIM / BN)           // 72
#define STAGES 4

#define A_TILE_BYTES (BM * 128)      // 16384
#define W_TILE_BYTES (BN * 128)      // 32768
#define STAGE_BYTES  (A_TILE_BYTES + W_TILE_BYTES)        // 49152
#define SMEM_TILE0   1024            // mbarriers live here
#define SMEM_TOTAL   (SMEM_TILE0 + STAGES * STAGE_BYTES)  // 197632 -> 1 CTA/SM

__device__ __align__(1024) unsigned char g_ap[(size_t)MDIM * KDIM * 4];
__device__ __align__(1024) unsigned char g_wp[(size_t)NDIM * KDIM * 4];

// ---------------------------------------------------------------------------
__device__ __forceinline__ uint32_t smem_u32(const void* p) {
    uint32_t a;
    asm("{ .reg .u64 t; cvta.to.shared.u64 t, %1; cvt.u32.u64 %0, t; }" : "=r"(a) : "l"(p));
    return a;
}
__device__ __forceinline__ float rna_tf32(float x) {
    uint32_t u;
    asm("cvt.rna.tf32.f32 %0, %1;" : "=r"(u) : "f"(x));
    return __uint_as_float(u);
}
__device__ __forceinline__ uint32_t lds32(uint32_t a) {
    uint32_t v;
    asm volatile("ld.shared.b32 %0, [%1];" : "=r"(v) : "r"(a));
    return v;
}
__device__ __forceinline__ void mma_tf32(float* d, const uint32_t* a, const uint32_t* b) {
    asm volatile(
        "mma.sync.aligned.m16n8k8.row.col.f32.tf32.tf32.f32 "
        "{%0,%1,%2,%3}, {%4,%5,%6,%7}, {%8,%9}, {%0,%1,%2,%3};"
        : "+f"(d[0]), "+f"(d[1]), "+f"(d[2]), "+f"(d[3])
        : "r"(a[0]), "r"(a[1]), "r"(a[2]), "r"(a[3]), "r"(b[0]), "r"(b[1]));
}

#define MBARRIER_INIT(addr, cnt) \
    asm volatile("mbarrier.init.shared.b64 [%0], %1;" :: "r"((uint32_t)(addr)), "r"((uint32_t)(cnt)) : "memory")
#define MBARRIER_EXPECT_TX(addr, bytes) \
    asm volatile("mbarrier.arrive.expect_tx.shared.b64 _, [%0], %1;" :: "r"((uint32_t)(addr)), "r"((uint32_t)(bytes)) : "memory")
#define MBARRIER_WAIT_PARITY(addr, par) do {                                    \
    uint32_t _m = (uint32_t)(addr), _p = (uint32_t)(par), _d;                   \
    asm volatile("{ .reg .pred p; mbarrier.try_wait.parity.acquire.cta.shared::cta.b64 p, [%1], %2; selp.b32 %0, 1, 0, p; }" \
                 : "=r"(_d) : "r"(_m), "r"(_p) : "memory");                     \
    if (!_d) {                                                                  \
        asm volatile("{ .reg .pred P1; WL_%=: mbarrier.try_wait.parity.acquire.cta.shared::cta.b64 P1, [%0], %1, 0x989680;" \
                     " @P1 bra.uni WD_%=; bra.uni WL_%=; WD_%=: }"              \
                     :: "r"(_m), "r"(_p) : "memory");                           \
    } } while (0)

__device__ __forceinline__ void bulk_g2s(uint32_t dst, const void* src,
                                         uint32_t bytes, uint32_t mbar) {
    asm volatile(
        "cp.async.bulk.shared::cta.global.mbarrier::complete_tx::bytes [%0], [%1], %2, [%3];"
        :: "r"(dst), "l"(__cvta_generic_to_global(src)), "r"(bytes), "r"(mbar) : "memory");
}

// ---------------------------------------------------------------------------
// Pack kernels (R3 layout, coalesced STG.128): tile rows x 32 tf32, 128B/row,
// SW128 swizzle: byte = row*128 + k*4, sw = byte ^ ((byte>>3)&0x70).
// ---------------------------------------------------------------------------
__global__ __launch_bounds__(256) void pack_a_kernel(const float* __restrict__ x) {
    size_t i = (size_t)blockIdx.x * 256 + threadIdx.x;
    if (i >= (size_t)MDIM * KDIM / 4) return;
    size_t f = i * 4;
    int m = (int)(f / KDIM);
    int k = (int)(f % KDIM);
    float4 v = *(const float4*)(x + f);
    uint32_t off = ((uint32_t)(m & 127) << 7) + ((uint32_t)(k & 31) << 2);
    uint32_t sw = off ^ ((off >> 3) & 0x70);
    unsigned char* dst = g_ap + ((size_t)(m >> 7) * KCHUNKS + (k >> 5)) * A_TILE_BYTES + sw;
    *(float4*)dst = make_float4(rna_tf32(v.x), rna_tf32(v.y), rna_tf32(v.z), rna_tf32(v.w));
}

__global__ __launch_bounds__(256) void pack_w_kernel(const float* __restrict__ w,
                                                     const float* __restrict__ scale) {
    size_t i = (size_t)blockIdx.x * 256 + threadIdx.x;
    if (i >= (size_t)NDIM * KDIM / 4) return;
    size_t f = i * 4;
    int n = (int)(f / KDIM);
    int k = (int)(f % KDIM);
    float4 v = *(const float4*)(w + f);
    float s = scale[(size_t)(n >> 7) * (KDIM / 128) + (k >> 7)];
    uint32_t off = ((uint32_t)(n & 255) << 7) + ((uint32_t)(k & 31) << 2);
    uint32_t sw = off ^ ((off >> 3) & 0x70);
    unsigned char* dst = g_wp + ((size_t)(n >> 8) * KCHUNKS + (k >> 5)) * W_TILE_BYTES + sw;
    *(float4*)dst = make_float4(rna_tf32(v.x * s), rna_tf32(v.y * s),
                                rna_tf32(v.z * s), rna_tf32(v.w * s));
}

// ---------------------------------------------------------------------------
// GEMM: 8 warps (2m x 4n), warp tile 64x64, mma m16n8k8 tf32.
// ---------------------------------------------------------------------------
__global__ __launch_bounds__(256, 1) void gemm_tf32_kernel(float* __restrict__ C) {
    extern __shared__ __align__(1024) unsigned char smem[];
    const uint32_t sb = smem_u32(smem);              // mbar region
    const uint32_t sd = sb + SMEM_TILE0;             // data stages
    const int tid = threadIdx.x;
    const int wid = tid >> 5;
    const int lane = tid & 31;

    // Grid swizzle: 8-wide n groups for L2 reuse.
    const int GN = 8;
    int bid = blockIdx.x;
    int grp = bid / (MTILES * GN);
    int rem = bid % (MTILES * GN);
    int bm = rem / GN;
    int bn = grp * GN + rem % GN;

    const unsigned char* aP = g_ap + (size_t)bm * KCHUNKS * A_TILE_BYTES;
    const unsigned char* wP = g_wp + (size_t)bn * KCHUNKS * W_TILE_BYTES;

    // full[s] mbarriers at sb + 8s.
    if (tid == 0) {
        for (int s = 0; s < STAGES; s++) MBARRIER_INIT(sb + 8 * s, 1);
    }
    __syncthreads();   // init visible before any bulk copy targets them

    auto issue = [&](int c) {
        if (c < KCHUNKS) {
            uint32_t s = (uint32_t)(c & (STAGES - 1));
            uint32_t mb = sb + 8 * s;
            uint32_t dst = sd + s * STAGE_BYTES;
            MBARRIER_EXPECT_TX(mb, STAGE_BYTES);
            bulk_g2s(dst, aP + (size_t)c * A_TILE_BYTES, A_TILE_BYTES, mb);
            bulk_g2s(dst + A_TILE_BYTES, wP + (size_t)c * W_TILE_BYTES, W_TILE_BYTES, mb);
        }
    };

    if (tid == 0) { issue(0); issue(1); issue(2); }

    const int tr = lane >> 2;
    const int tc = lane & 3;
    const int wm = wid & 1;
    const int wn = wid >> 1;
    const int m_base = wm * 64;
    const int n_base = wn * 64;

    uint32_t baseA0[4], baseA1[4], baseB[8];
#pragma unroll
    for (int mi = 0; mi < 4; mi++) {
        baseA0[mi] = (uint32_t)(m_base + mi * 16 + tr) * 128 + tc * 4;
        baseA1[mi] = baseA0[mi] + 8 * 128;
    }
#pragma unroll
    for (int ni = 0; ni < 8; ni++)
        baseB[ni] = (uint32_t)A_TILE_BYTES + (uint32_t)(n_base + ni * 8 + tr) * 128 + tc * 4;

    float acc[4][8][4];
#pragma unroll
    for (int mi = 0; mi < 4; mi++)
#pragma unroll
        for (int ni = 0; ni < 8; ni++)
#pragma unroll
            for (int q = 0; q < 4; q++) acc[mi][ni][q] = 0.f;

#pragma unroll 1
    for (int c = 0; c < KCHUNKS; c++) {
        const uint32_t s = (uint32_t)(c & (STAGES - 1));
        // Wait for chunk c's data. Phase flips each time the stage recycles.
        MBARRIER_WAIT_PARITY(sb + 8 * s, (c >> 2) & 1);

        const uint32_t st = sd + s * STAGE_BYTES;
#pragma unroll
        for (int ks = 0; ks < 4; ks++) {
            const uint32_t offe = (uint32_t)((2 * ks) ^ tr) << 4;
            const uint32_t offo = offe ^ 16;
            uint32_t a[4][4];
#pragma unroll
            for (int mi = 0; mi < 4; mi++) {
                a[mi][0] = lds32(st + baseA0[mi] + offe);
                a[mi][1] = lds32(st + baseA1[mi] + offe);
                a[mi][2] = lds32(st + baseA0[mi] + offo);
                a[mi][3] = lds32(st + baseA1[mi] + offo);
            }
            uint32_t b[8][2];
#pragma unroll
            for (int ni = 0; ni < 8; ni++) {
                b[ni][0] = lds32(st + baseB[ni] + offe);
                b[ni][1] = lds32(st + baseB[ni] + offo);
            }
#pragma unroll
            for (int mi = 0; mi < 4; mi++)
#pragma unroll
                for (int ni = 0; ni < 8; ni++)
                    mma_tf32(acc[mi][ni], a[mi], b[ni]);
        }

        // All threads done reading stage s for chunk c; stage (c+3)&3 ==
        // (c-1)&3 was finished last iteration, so refilling it is safe.
        __syncthreads();
        if (tid == 0) issue(c + 3);
    }

    // Epilogue.
#pragma unroll
    for (int mi = 0; mi < 4; mi++) {
        size_t r0 = (size_t)bm * BM + m_base + mi * 16 + tr;
        float* p0 = C + r0 * NDIM + (size_t)bn * BN + n_base + 2 * tc;
        float* p1 = p0 + (size_t)8 * NDIM;
#pragma unroll
        for (int ni = 0; ni < 8; ni++) {
            *(float2*)(p0 + ni * 8) = make_float2(acc[mi][ni][0], acc[mi][ni][1]);
            *(float2*)(p1 + ni * 8) = make_float2(acc[mi][ni][2], acc[mi][ni][3]);
        }
    }
}

// ---------------------------------------------------------------------------
extern "C" void kernel_launch(void* const* d_in, const int* in_sizes, int n_in,
                              void* d_out, int out_size) {
    const float* x      = (const float*)d_in[0];
    const float* weight = (const float*)d_in[1];
    const float* scale  = (const float*)d_in[2];
    float* out          = (float*)d_out;

    cudaFuncSetAttribute(gemm_tf32_kernel,
                         cudaFuncAttributeMaxDynamicSharedMemorySize, SMEM_TOTAL);

    size_t a4 = (size_t)MDIM * KDIM / 4;
    size_t w4 = (size_t)NDIM * KDIM / 4;
    pack_a_kernel<<<(unsigned)((a4 + 255) / 256), 256>>>(x);
    pack_w_kernel<<<(unsigned)((w4 + 255) / 256), 256>>>(weight, scale);
    gemm_tf32_kernel<<<MTILES * NTILES, 256, SMEM_TOTAL>>>(out);
}

// round 7
// speedup vs baseline: 5.8620x; 1.7991x over previous
#include <cuda_runtime.h>
#include <cuda_fp16.h>
#include <cstdint>

// ---------------------------------------------------------------------------
// C[4096,18432] = A[4096,7168] * W[18432,7168]^T, per-128x128 block scales.
//  Pass 1: pack kernels -> dequant + cvt to fp16 (RN) + SW128 swizzle,
//          tile-major (coalesced 16B stores).
//  Pass 2: GEMM -> mma.sync.m16n8k16.f32.f16.f16.f32 (2x tf32 rate, same
//          10-bit mantissa), cp.async.cg 4-stage pipeline (proven R3 shape).
// ---------------------------------------------------------------------------

#define MDIM 4096
#define NDIM 18432
#define KDIM 7168
#define BM 128
#define BN 256
#define BK 64                        // 64 fp16 = 128B row
#define KCHUNKS (KDIM / BK)          // 112
#define MTILES (MDIM / BM)           // 32
#define NTILES (NDIM / BN)           // 72

#define A_TILE_BYTES (BM * 128)      // 16384 (128 rows x 64 fp16)
#define W_TILE_BYTES (BN * 128)      // 32768 (256 rows x 64 fp16)
#define STAGE_BYTES  (A_TILE_BYTES + W_TILE_BYTES)   // 49152
#define SMEM_TOTAL   (4 * STAGE_BYTES)               // 196608, 1 CTA/SM

__device__ __align__(1024) unsigned char g_ap[(size_t)MDIM * KDIM * 2];  // 58 MB
__device__ __align__(1024) unsigned char g_wp[(size_t)NDIM * KDIM * 2];  // 264 MB

// ---------------------------------------------------------------------------
__device__ __forceinline__ uint32_t smem_u32(const void* p) {
    uint32_t a;
    asm("{ .reg .u64 t; cvta.to.shared.u64 t, %1; cvt.u32.u64 %0, t; }" : "=r"(a) : "l"(p));
    return a;
}
__device__ __forceinline__ uint32_t lds32(uint32_t a) {
    uint32_t v;
    asm volatile("ld.shared.b32 %0, [%1];" : "=r"(v) : "r"(a));
    return v;
}
__device__ __forceinline__ void cp16(uint32_t dst, const void* src) {
    asm volatile("cp.async.cg.shared.global [%0], [%1], 16;"
                 :: "r"(dst), "l"(__cvta_generic_to_global(src)) : "memory");
}
__device__ __forceinline__ void mma_f16(float* d, const uint32_t* a, const uint32_t* b) {
    asm volatile(
        "mma.sync.aligned.m16n8k16.row.col.f32.f16.f16.f32 "
        "{%0,%1,%2,%3}, {%4,%5,%6,%7}, {%8,%9}, {%0,%1,%2,%3};"
        : "+f"(d[0]), "+f"(d[1]), "+f"(d[2]), "+f"(d[3])
        : "r"(a[0]), "r"(a[1]), "r"(a[2]), "r"(a[3]), "r"(b[0]), "r"(b[1]));
}
__device__ __forceinline__ uint32_t h2(float lo, float hi) {
    __half2 h = __floats2half2_rn(lo, hi);       // RN, unbiased
    return *reinterpret_cast<uint32_t*>(&h);
}

// ---------------------------------------------------------------------------
// Pack layout: tile-major; tile row = 64 fp16 = 128B, SW128 swizzle:
// byte = row*128 + k*2, sw = byte ^ ((byte>>3)&0x70). Each thread converts
// 8 floats -> one 16B store (swizzle preserves 16B blocks).
// ---------------------------------------------------------------------------
__global__ __launch_bounds__(256) void pack_a_kernel(const float* __restrict__ x) {
    size_t i = (size_t)blockIdx.x * 256 + threadIdx.x;
    if (i >= (size_t)MDIM * KDIM / 8) return;
    size_t f = i * 8;
    int m = (int)(f / KDIM);
    int k = (int)(f % KDIM);
    float4 v0 = *(const float4*)(x + f);
    float4 v1 = *(const float4*)(x + f + 4);
    uint32_t off = ((uint32_t)(m & 127) << 7) + ((uint32_t)(k & 63) << 1);
    uint32_t sw = off ^ ((off >> 3) & 0x70);
    unsigned char* dst = g_ap + ((size_t)(m >> 7) * KCHUNKS + (k >> 6)) * A_TILE_BYTES + sw;
    *(uint4*)dst = make_uint4(h2(v0.x, v0.y), h2(v0.z, v0.w), h2(v1.x, v1.y), h2(v1.z, v1.w));
}

__global__ __launch_bounds__(256) void pack_w_kernel(const float* __restrict__ w,
                                                     const float* __restrict__ scale) {
    size_t i = (size_t)blockIdx.x * 256 + threadIdx.x;
    if (i >= (size_t)NDIM * KDIM / 8) return;
    size_t f = i * 8;
    int n = (int)(f / KDIM);
    int k = (int)(f % KDIM);
    float4 v0 = *(const float4*)(w + f);
    float4 v1 = *(const float4*)(w + f + 4);
    float s = scale[(size_t)(n >> 7) * (KDIM / 128) + (k >> 7)];
    uint32_t off = ((uint32_t)(n & 255) << 7) + ((uint32_t)(k & 63) << 1);
    uint32_t sw = off ^ ((off >> 3) & 0x70);
    unsigned char* dst = g_wp + ((size_t)(n >> 8) * KCHUNKS + (k >> 6)) * W_TILE_BYTES + sw;
    *(uint4*)dst = make_uint4(h2(v0.x * s, v0.y * s), h2(v0.z * s, v0.w * s),
                              h2(v1.x * s, v1.y * s), h2(v1.z * s, v1.w * s));
}

// ---------------------------------------------------------------------------
// GEMM: 8 warps (2m x 4n), warp tile 64x64, mma m16n8k16 fp16.
// ---------------------------------------------------------------------------
__global__ __launch_bounds__(256, 1) void gemm_f16_kernel(float* __restrict__ C) {
    extern __shared__ __align__(1024) unsigned char smem[];
    const uint32_t sb = smem_u32(smem);
    const int tid = threadIdx.x;
    const int wid = tid >> 5;
    const int lane = tid & 31;

    // Grid swizzle: 8-wide n groups for L2 reuse.
    const int GN = 8;
    int bid = blockIdx.x;
    int grp = bid / (MTILES * GN);
    int rem = bid % (MTILES * GN);
    int bm = rem / GN;
    int bn = grp * GN + rem % GN;

    const unsigned char* aP = g_ap + (size_t)bm * KCHUNKS * A_TILE_BYTES;
    const unsigned char* wP = g_wp + (size_t)bn * KCHUNKS * W_TILE_BYTES;

    const int tr = lane >> 2;            // 0..7
    const int tc = lane & 3;             // 0..3
    const int wm = wid & 1;
    const int wn = wid >> 1;
    const int m_base = wm * 64;
    const int n_base = wn * 64;

    // Row base addresses (swizzle xors col bits[6:4] with tr).
    uint32_t rowA[4], rowB[8];
#pragma unroll
    for (int mi = 0; mi < 4; mi++)
        rowA[mi] = (uint32_t)(m_base + mi * 16 + tr) * 128;
#pragma unroll
    for (int ni = 0; ni < 8; ni++)
        rowB[ni] = (uint32_t)A_TILE_BYTES + (uint32_t)(n_base + ni * 8 + tr) * 128;

    float acc[4][8][4];
#pragma unroll
    for (int mi = 0; mi < 4; mi++)
#pragma unroll
        for (int ni = 0; ni < 8; ni++)
#pragma unroll
            for (int q = 0; q < 4; q++) acc[mi][ni][q] = 0.f;

    auto issue = [&](int c) {
        if (c < KCHUNKS) {
            const unsigned char* srcA = aP + (size_t)c * A_TILE_BYTES;
            const unsigned char* srcW = wP + (size_t)c * W_TILE_BYTES;
            uint32_t dst = sb + (uint32_t)(c & 3) * STAGE_BYTES;
#pragma unroll
            for (int i = 0; i < 4; i++) {
                int idx = tid + i * 256;
                cp16(dst + idx * 16, srcA + idx * 16);
            }
#pragma unroll
            for (int i = 0; i < 8; i++) {
                int idx = tid + i * 256;
                cp16(dst + A_TILE_BYTES + idx * 16, srcW + idx * 16);
            }
        }
        asm volatile("cp.async.commit_group;" ::: "memory");
    };

    issue(0);
    issue(1);
    issue(2);

#pragma unroll 1
    for (int c = 0; c < KCHUNKS; c++) {
        asm volatile("cp.async.wait_group 2;" ::: "memory");
        __syncthreads();

        const uint32_t st = sb + (uint32_t)(c & 3) * STAGE_BYTES;
#pragma unroll
        for (int ks = 0; ks < 4; ks++) {            // k16 block within chunk
            // col byte = ks*32 + tc*4 (k = ks*16 + 2tc), bit4 clear -> ^16 ok
            const uint32_t offe = (uint32_t)(ks * 32 + tc * 4) ^ ((uint32_t)tr << 4);
            const uint32_t offo = offe ^ 16;        // k + 8
            uint32_t a[4][4];
#pragma unroll
            for (int mi = 0; mi < 4; mi++) {
                a[mi][0] = lds32(st + rowA[mi] + offe);          // (tr,   k0)
                a[mi][1] = lds32(st + rowA[mi] + 1024 + offe);   // (tr+8, k0)
                a[mi][2] = lds32(st + rowA[mi] + offo);          // (tr,   k8)
                a[mi][3] = lds32(st + rowA[mi] + 1024 + offo);   // (tr+8, k8)
            }
            uint32_t b[8][2];
#pragma unroll
            for (int ni = 0; ni < 8; ni++) {
                b[ni][0] = lds32(st + rowB[ni] + offe);
                b[ni][1] = lds32(st + rowB[ni] + offo);
            }
#pragma unroll
            for (int mi = 0; mi < 4; mi++)
#pragma unroll
                for (int ni = 0; ni < 8; ni++)
                    mma_f16(acc[mi][ni], a[mi], b[ni]);
        }
        __syncthreads();          // all reads of stage (c-1)&3 done before refill
        issue(c + 3);
    }

    // Epilogue: c0,c1 -> (row tr, cols 2tc,2tc+1); c2,c3 -> (row tr+8).
#pragma unroll
    for (int mi = 0; mi < 4; mi++) {
        size_t r0 = (size_t)bm * BM + m_base + mi * 16 + tr;
        float* p0 = C + r0 * NDIM + (size_t)bn * BN + n_base + 2 * tc;
        float* p1 = p0 + (size_t)8 * NDIM;
#pragma unroll
        for (int ni = 0; ni < 8; ni++) {
            *(float2*)(p0 + ni * 8) = make_float2(acc[mi][ni][0], acc[mi][ni][1]);
            *(float2*)(p1 + ni * 8) = make_float2(acc[mi][ni][2], acc[mi][ni][3]);
        }
    }
}

// ---------------------------------------------------------------------------
extern "C" void kernel_launch(void* const* d_in, const int* in_sizes, int n_in,
                              void* d_out, int out_size) {
    const float* x      = (const float*)d_in[0];
    const float* weight = (const float*)d_in[1];
    const float* scale  = (const float*)d_in[2];
    float* out          = (float*)d_out;

    cudaFuncSetAttribute(gemm_f16_kernel,
                         cudaFuncAttributeMaxDynamicSharedMemorySize, SMEM_TOTAL);

    size_t a8 = (size_t)MDIM * KDIM / 8;
    size_t w8 = (size_t)NDIM * KDIM / 8;
    pack_a_kernel<<<(unsigned)((a8 + 255) / 256), 256>>>(x);
    pack_w_kernel<<<(unsigned)((w8 + 255) / 256), 256>>>(weight, scale);
    gemm_f16_kernel<<<MTILES * NTILES, 256, SMEM_TOTAL>>>(out);
}